// round 17
// baseline (speedup 1.0000x reference)
#include <cuda_runtime.h>
#include <math.h>

#define C_DIM 128
#define S_DIM 4096
#define HW 176          // 16 * 11
#define HW4 44
#define B_SEG 32
#define O_DIM 256
#define OT 16           // o per conv block
#define CPIPE 4
#define PART_LEN 44
#define GEM_EPS 1e-6f
#define NEG_INF -3.402823466e38f

// scratch: pooled[b][c][hw]
__device__ float g_pooled[B_SEG * C_DIM * HW];

__device__ __forceinline__ float4 max4(float4 a, float4 b) {
    float4 r;
    r.x = fmaxf(a.x, b.x); r.y = fmaxf(a.y, b.y);
    r.z = fmaxf(a.z, b.z); r.w = fmaxf(a.w, b.w);
    return r;
}
__device__ __forceinline__ unsigned long long pack2(float v) {
    unsigned long long r;
    asm("mov.b64 %0, {%1, %1};" : "=l"(r) : "f"(v));
    return r;
}
__device__ __forceinline__ void unpack2(unsigned long long v, float& lo, float& hi) {
    asm("mov.b64 {%0, %1}, %2;" : "=f"(lo), "=f"(hi) : "l"(v));
}
__device__ __forceinline__ void ffma2(unsigned long long& d,
                                      unsigned long long a, unsigned long long b) {
    asm("fma.rn.f32x2 %0, %1, %2, %0;" : "+l"(d) : "l"(a), "l"(b));
}
__device__ __forceinline__ void fadd2(unsigned long long& d, unsigned long long a) {
    asm("add.rn.f32x2 %0, %0, %1;" : "+l"(d) : "l"(a));
}
// GeM power, fast path for pe == 6.5: (v^3)^2 * sqrt(v).
__device__ __forceinline__ float gem_pow(float x, float pe, bool fast65) {
    float v = fmaxf(x, GEM_EPS);
    if (fast65) {
        float v3 = v * v * v;
        return v3 * v3 * sqrtf(v);
    }
    return exp2f(pe * __log2f(v));
}

// ---------------------------------------------------------------------------
// Kernel 1: ragged segment max — EXACT R5/R7 config (~59 us, 6.25 TB/s).
// ---------------------------------------------------------------------------
__global__ void __launch_bounds__(352) seg_max_kernel(
    const float* __restrict__ x, const int* __restrict__ seqL)
{
    int blk = blockIdx.x;
    int b = blk & (B_SEG - 1);
    int c = blk >> 5;

    __shared__ int sh[2];
    __shared__ float4 sm[8 * HW4];

    if (threadIdx.x == 0) {
        int s0 = 0;
        #pragma unroll
        for (int i = 0; i < B_SEG; i++) s0 += (i < b) ? seqL[i] : 0;
        sh[0] = s0;
        sh[1] = seqL[b];
    }
    __syncthreads();

    int tid = threadIdx.x;
    int sg  = tid / HW4;
    int col = tid % HW4;

    int s0  = sh[0];
    int len = sh[1];

    const float4* bp = reinterpret_cast<const float4*>(x)
                     + (size_t)c * (S_DIM * HW4) + (size_t)s0 * HW4 + col;

    float4 m = make_float4(NEG_INF, NEG_INF, NEG_INF, NEG_INF);
    int s = sg;
    for (; s + 56 < len; s += 64) {
        float4 a0 = __ldcs(&bp[(size_t)(s +  0) * HW4]);
        float4 a1 = __ldcs(&bp[(size_t)(s +  8) * HW4]);
        float4 a2 = __ldcs(&bp[(size_t)(s + 16) * HW4]);
        float4 a3 = __ldcs(&bp[(size_t)(s + 24) * HW4]);
        float4 a4 = __ldcs(&bp[(size_t)(s + 32) * HW4]);
        float4 a5 = __ldcs(&bp[(size_t)(s + 40) * HW4]);
        float4 a6 = __ldcs(&bp[(size_t)(s + 48) * HW4]);
        float4 a7 = __ldcs(&bp[(size_t)(s + 56) * HW4]);
        m = max4(m, max4(max4(max4(a0, a1), max4(a2, a3)),
                         max4(max4(a4, a5), max4(a6, a7))));
    }
    for (; s < len; s += 8) {
        m = max4(m, __ldcs(&bp[(size_t)s * HW4]));
    }

    sm[sg * HW4 + col] = m;
    __syncthreads();

    if (tid < HW4) {
        float4 r = sm[tid];
        #pragma unroll
        for (int g = 1; g < 8; g++) r = max4(r, sm[g * HW4 + tid]);
        reinterpret_cast<float4*>(g_pooled)[(size_t)(b * C_DIM + c) * HW4 + tid] = r;
    }
}

// ---------------------------------------------------------------------------
// Kernel 2: conv + GeM, zero-mov inner loop.
// acc lanes = (hw_even, hw_odd): a-operand is the raw u64 half of the pooled
// float4 (no splat). W pre-splatted in smem as (w,w) u64 -> b-operand is a
// direct LDS.128. Per thread per cc: 1 LDG.128 + 4 LDS.128 + 16 FFMA2.
// Grid (16 o-tiles, 32 b) = 512 blocks, 176 thr = 2 c-halves x 2 o-groups
// x 44 hw-quads. Packed u64 smem reduction (add.f32x2) across c-halves.
// ---------------------------------------------------------------------------
__global__ void __launch_bounds__(176) conv_gem_kernel(
    const float* __restrict__ Wmat, const float* __restrict__ p,
    float* __restrict__ out)
{
    __shared__ __align__(16) unsigned long long ws2[C_DIM * OT];   // 16 KB splat W
    __shared__ __align__(16) unsigned long long redu[88 * 16];     // 11 KB
    __shared__ float pp[4];
    float* red2 = reinterpret_cast<float*>(ws2);   // overlay: [44][16] floats

    int b   = blockIdx.y;
    int o0  = blockIdx.x * OT;
    int tid = threadIdx.x;
    int ch  = tid / 88;           // c-half 0/1
    int r   = tid % 88;
    int og  = r / HW4;            // o-group 0/1 (8 o each)
    int q   = r % HW4;            // hw quad 0..43

    if (tid < 4) pp[tid] = p[tid];
    for (int i = tid; i < C_DIM * OT; i += 176) {
        int cc = i >> 4;
        int j  = i & (OT - 1);
        ws2[i] = pack2(Wmat[(o0 + j) * C_DIM + cc]);
    }
    __syncthreads();

    unsigned long long acc[16];   // [0..7]=o for hw01, [8..15]=o for hw23
    #pragma unroll
    for (int k = 0; k < 16; k++) acc[k] = 0ULL;

    {
        int cbase = ch * 64;
        const ulonglong2* pb = reinterpret_cast<const ulonglong2*>(
            g_pooled + (size_t)b * C_DIM * HW) + (size_t)cbase * HW4 + q;
        const unsigned long long* wb = ws2 + cbase * OT + og * 8;

        ulonglong2 pv[CPIPE];
        #pragma unroll
        for (int j = 0; j < CPIPE; j++)
            pv[j] = __ldg(&pb[(size_t)j * HW4]);

        #pragma unroll
        for (int c0 = 0; c0 < 64; c0 += CPIPE) {
            ulonglong2 nv[CPIPE];
            if (c0 + CPIPE < 64) {
                #pragma unroll
                for (int j = 0; j < CPIPE; j++)
                    nv[j] = __ldg(&pb[(size_t)(c0 + CPIPE + j) * HW4]);
            }
            #pragma unroll
            for (int j = 0; j < CPIPE; j++) {
                const ulonglong2* wr = reinterpret_cast<const ulonglong2*>(
                    wb + (c0 + j) * OT);
                ulonglong2 w0 = wr[0];   // splats o0, o1
                ulonglong2 w1 = wr[1];   // splats o2, o3
                ulonglong2 w2 = wr[2];   // splats o4, o5
                ulonglong2 w3 = wr[3];   // splats o6, o7
                unsigned long long a01 = pv[j].x;   // (hw0, hw1)
                unsigned long long a23 = pv[j].y;   // (hw2, hw3)
                ffma2(acc[ 0], a01, w0.x); ffma2(acc[ 1], a01, w0.y);
                ffma2(acc[ 2], a01, w1.x); ffma2(acc[ 3], a01, w1.y);
                ffma2(acc[ 4], a01, w2.x); ffma2(acc[ 5], a01, w2.y);
                ffma2(acc[ 6], a01, w3.x); ffma2(acc[ 7], a01, w3.y);
                ffma2(acc[ 8], a23, w0.x); ffma2(acc[ 9], a23, w0.y);
                ffma2(acc[10], a23, w1.x); ffma2(acc[11], a23, w1.y);
                ffma2(acc[12], a23, w2.x); ffma2(acc[13], a23, w2.y);
                ffma2(acc[14], a23, w3.x); ffma2(acc[15], a23, w3.y);
            }
            #pragma unroll
            for (int j = 0; j < CPIPE; j++) pv[j] = nv[j];
        }
    }

    // c-half 1 dumps packed accumulators
    if (ch == 1) {
        ulonglong2* rp = reinterpret_cast<ulonglong2*>(redu + r * 16);
        #pragma unroll
        for (int k = 0; k < 8; k++)
            rp[k] = make_ulonglong2(acc[2 * k], acc[2 * k + 1]);
    }
    __syncthreads();

    if (ch == 0) {
        const ulonglong2* rp = reinterpret_cast<const ulonglong2*>(redu + r * 16);
        #pragma unroll
        for (int k = 0; k < 8; k++) {
            ulonglong2 v = rp[k];
            fadd2(acc[2 * k], v.x);
            fadd2(acc[2 * k + 1], v.y);
        }
    }
    __syncthreads();   // redu done; ws2 free to overlay as red2

    if (ch == 0) {
        float pe = pp[q / 11];
        bool fast65 = (pe == 6.5f);
        #pragma unroll
        for (int o = 0; o < 8; o++) {
            float v0, v1, v2, v3;
            unpack2(acc[o],     v0, v1);
            unpack2(acc[8 + o], v2, v3);
            float s = gem_pow(v0, pe, fast65) + gem_pow(v1, pe, fast65)
                    + gem_pow(v2, pe, fast65) + gem_pow(v3, pe, fast65);
            red2[q * OT + og * 8 + o] = s;
        }
    }
    __syncthreads();

    // 64 threads: (o, part) -> sum 11 quad-partials, final root
    if (tid < OT * 4) {
        int o    = tid >> 2;
        int part = tid & 3;
        float sum = 0.0f;
        #pragma unroll
        for (int j = 0; j < 11; j++)
            sum += red2[(part * 11 + j) * OT + o];
        float pe = pp[part];
        float mean = sum * (1.0f / (float)PART_LEN);
        float gv = (mean > 0.0f) ? exp2f(__log2f(mean) / pe) : 0.0f;
        out[((size_t)b * O_DIM + o0 + o) * 4 + part] = gv;
    }
}

extern "C" void kernel_launch(void* const* d_in, const int* in_sizes, int n_in,
                              void* d_out, int out_size)
{
    const float* x    = (const float*)d_in[0];
    const int*   seqL = (const int*)d_in[1];
    const float* Wm   = (const float*)d_in[2];
    const float* p    = (const float*)d_in[3];
    float* out = (float*)d_out;

    seg_max_kernel<<<B_SEG * C_DIM, 352>>>(x, seqL);

    dim3 grid2(O_DIM / OT, B_SEG);
    conv_gem_kernel<<<grid2, 176>>>(Wm, p, out);
}